// round 4
// baseline (speedup 1.0000x reference)
#include <cuda_runtime.h>
#include <cuda_bf16.h>

#define N_NODES  100000
#define N_EDGES  1600000
#define N_GRAPHS 64
#define HID      64
#define LN_EPS   1e-5f
#define FULL     0xffffffffu

// -------- persistent device scratch --------
__device__ float4 g_acc[N_NODES];     // sum_e ex * x[src]  (4-dim!)
__device__ float  g_den[N_NODES];     // sum_e ex
__device__ float  g_adl[N_NODES];     // att.(x@W_l) per node (no bias)
__device__ float  g_ad [N_NODES];     // att.(x@W_r) + att.(b_l+b_r) per node
__device__ float4 g_wal, g_war;       // W_l^T att, W_r^T att
__device__ float  g_cad;              // att.(b_l+b_r)
__device__ float  g_sW, g_sB;         // sum ln_w*lin_w, sum ln_b*lin_w + lin_b
__device__ double g_S[N_GRAPHS];
__device__ int    g_cnt[N_GRAPHS];
__device__ double g_sum, g_sq;

// -------- kernel 0: zero accumulators --------
__global__ void k_zero() {
    int i = blockIdx.x * blockDim.x + threadIdx.x;
    int stride = gridDim.x * blockDim.x;
    for (int t = i; t < N_NODES; t += stride) {
        g_acc[t] = make_float4(0.f, 0.f, 0.f, 0.f);
        g_den[t] = 0.f;
    }
    if (i < N_GRAPHS) { g_S[i] = 0.0; g_cnt[i] = 0; }
    if (i == 0) { g_sum = 0.0; g_sq = 0.0; }
}

// -------- kernel 1: tiny constants (one warp) --------
__global__ void k_const(const float* __restrict__ W_l, const float* __restrict__ W_r,
                        const float* __restrict__ att,
                        const float* __restrict__ b_l, const float* __restrict__ b_r,
                        const float* __restrict__ ln_w, const float* __restrict__ ln_b,
                        const float* __restrict__ lin_w, const float* __restrict__ lin_b) {
    int c = threadIdx.x;                 // 0..31, handles channels c and c+32
    float a0 = att[c], a1 = att[c + 32];
    float p0 = W_l[0*64+c]*a0 + W_l[0*64+c+32]*a1;
    float p1 = W_l[1*64+c]*a0 + W_l[1*64+c+32]*a1;
    float p2 = W_l[2*64+c]*a0 + W_l[2*64+c+32]*a1;
    float p3 = W_l[3*64+c]*a0 + W_l[3*64+c+32]*a1;
    float r0 = W_r[0*64+c]*a0 + W_r[0*64+c+32]*a1;
    float r1 = W_r[1*64+c]*a0 + W_r[1*64+c+32]*a1;
    float r2 = W_r[2*64+c]*a0 + W_r[2*64+c+32]*a1;
    float r3 = W_r[3*64+c]*a0 + W_r[3*64+c+32]*a1;
    float bb = (b_l[c]+b_r[c])*a0 + (b_l[c+32]+b_r[c+32])*a1;
    float sw = ln_w[c]*lin_w[c] + ln_w[c+32]*lin_w[c+32];
    float sb = ln_b[c]*lin_w[c] + ln_b[c+32]*lin_w[c+32];
    #pragma unroll
    for (int off = 16; off > 0; off >>= 1) {
        p0 += __shfl_xor_sync(FULL, p0, off);
        p1 += __shfl_xor_sync(FULL, p1, off);
        p2 += __shfl_xor_sync(FULL, p2, off);
        p3 += __shfl_xor_sync(FULL, p3, off);
        r0 += __shfl_xor_sync(FULL, r0, off);
        r1 += __shfl_xor_sync(FULL, r1, off);
        r2 += __shfl_xor_sync(FULL, r2, off);
        r3 += __shfl_xor_sync(FULL, r3, off);
        bb += __shfl_xor_sync(FULL, bb, off);
        sw += __shfl_xor_sync(FULL, sw, off);
        sb += __shfl_xor_sync(FULL, sb, off);
    }
    if (c == 0) {
        g_wal = make_float4(p0, p1, p2, p3);
        g_war = make_float4(r0, r1, r2, r3);
        g_cad = bb;
        g_sW = sw;
        g_sB = sb + lin_b[0];
    }
}

// -------- kernel 2: per-node linear attention scalars --------
__global__ void k_pre(const float* __restrict__ x) {
    int n = blockIdx.x * blockDim.x + threadIdx.x;
    if (n >= N_NODES) return;
    float4 wal = g_wal, war = g_war;
    float4 xn = ((const float4*)x)[n];
    g_adl[n] = xn.x*wal.x + xn.y*wal.y + xn.z*wal.z + xn.w*wal.w;
    g_ad [n] = xn.x*war.x + xn.y*war.y + xn.z*war.z + xn.w*war.w + g_cad;
}

// -------- kernel 3: edge-parallel attention + 4-dim atomic aggregation --------
// warp = 2 edges; 16 lanes per edge; lane j owns channels [4j, 4j+4)
__global__ void __launch_bounds__(256)
k_edge(const int* __restrict__ ei,
       const float* __restrict__ x,
       const float* __restrict__ W_l, const float* __restrict__ W_r,
       const float* __restrict__ att,
       const float* __restrict__ b_l, const float* __restrict__ b_r) {
    int gtid = blockIdx.x * blockDim.x + threadIdx.x;
    int lane = threadIdx.x & 31;
    int half = lane >> 4;
    int j    = lane & 15;
    int e = (gtid >> 5) * 2 + half;    // grid sized exactly: N_EDGES covered

    const float4* x4  = (const float4*)x;
    const float4* wl4 = (const float4*)W_l;
    const float4* wr4 = (const float4*)W_r;

    float4 wl0 = wl4[j], wl1 = wl4[16 + j], wl2 = wl4[32 + j], wl3 = wl4[48 + j];
    float4 wr0 = wr4[j], wr1 = wr4[16 + j], wr2 = wr4[32 + j], wr3 = wr4[48 + j];
    float4 av  = ((const float4*)att)[j];
    float4 bl4 = ((const float4*)b_l)[j];
    float4 br4 = ((const float4*)b_r)[j];
    float4 brl = make_float4(bl4.x + br4.x, bl4.y + br4.y, bl4.z + br4.z, bl4.w + br4.w);

    int src = ei[e];
    int dst = ei[N_EDGES + e];

    float4 xs = x4[src];   // 16B broadcast within 16-lane group (L2/L1-resident)
    float4 xd = x4[dst];

    // h_c = x[src].Wl_c + x[dst].Wr_c + (bl+br)_c   for this lane's 4 channels
    float h0 = brl.x + xs.x*wl0.x + xs.y*wl1.x + xs.z*wl2.x + xs.w*wl3.x
                     + xd.x*wr0.x + xd.y*wr1.x + xd.z*wr2.x + xd.w*wr3.x;
    float h1 = brl.y + xs.x*wl0.y + xs.y*wl1.y + xs.z*wl2.y + xs.w*wl3.y
                     + xd.x*wr0.y + xd.y*wr1.y + xd.z*wr2.y + xd.w*wr3.y;
    float h2 = brl.z + xs.x*wl0.z + xs.y*wl1.z + xs.z*wl2.z + xs.w*wl3.z
                     + xd.x*wr0.z + xd.y*wr1.z + xd.z*wr2.z + xd.w*wr3.z;
    float h3 = brl.w + xs.x*wl0.w + xs.y*wl1.w + xs.z*wl2.w + xs.w*wl3.w
                     + xd.x*wr0.w + xd.y*wr1.w + xd.z*wr2.w + xd.w*wr3.w;

    // 0.4 * sum att*|h|   (leaky = 0.6h + 0.4|h|; linear part via adl/ad)
    float eabs = av.x * fabsf(h0);
    eabs = fmaf(av.y, fabsf(h1), eabs);
    eabs = fmaf(av.z, fabsf(h2), eabs);
    eabs = fmaf(av.w, fabsf(h3), eabs);
    eabs += __shfl_xor_sync(FULL, eabs, 8);
    eabs += __shfl_xor_sync(FULL, eabs, 4);
    eabs += __shfl_xor_sync(FULL, eabs, 2);
    eabs += __shfl_xor_sync(FULL, eabs, 1);

    if (j == 0) {
        float elin = g_adl[src] + g_ad[dst];
        float ex = __expf(fmaf(0.4f, eabs, 0.6f * elin));  // softmax shift cancels
        float* accp = (float*)&g_acc[dst];
        asm volatile("red.global.add.v4.f32 [%0], {%1,%2,%3,%4};"
                     :: "l"(accp), "f"(ex*xs.x), "f"(ex*xs.y), "f"(ex*xs.z), "f"(ex*xs.w)
                     : "memory");
        asm volatile("red.global.add.f32 [%0], %1;"
                     :: "l"(&g_den[dst]), "f"(ex) : "memory");
    }
}

// -------- kernel 4: node finalize + LN/pool stats --------
// warp = 2 nodes; 16 lanes per node; lane j owns channels [4j, 4j+4)
__global__ void k_node(const float* __restrict__ W_l, const float* __restrict__ b_l,
                       const float* __restrict__ conv_bias,
                       const float* __restrict__ ln_w, const float* __restrict__ lin_w,
                       const int* __restrict__ batch) {
    __shared__ float sS[N_GRAPHS];
    __shared__ int   sC[N_GRAPHS];
    __shared__ float sSum, sSq;
    int tid = threadIdx.x;
    if (tid < N_GRAPHS) { sS[tid] = 0.f; sC[tid] = 0; }
    if (tid == 0) { sSum = 0.f; sSq = 0.f; }
    __syncthreads();

    int lane = tid & 31;
    int half = lane >> 4;
    int j    = lane & 15;
    int n = ((blockIdx.x * blockDim.x + tid) >> 5) * 2 + half;

    const float4* wl4 = (const float4*)W_l;
    float4 wl0 = wl4[j], wl1 = wl4[16 + j], wl2 = wl4[32 + j], wl3 = wl4[48 + j];
    float4 bl4 = ((const float4*)b_l)[j];
    float4 cb  = ((const float4*)conv_bias)[j];
    float4 lw  = ((const float4*)ln_w)[j];
    float4 pw  = ((const float4*)lin_w)[j];

    float4 acc = g_acc[n];
    float  den = g_den[n];
    float invd = den > 0.f ? 1.f / den : 0.f;
    float bsel = den > 0.f ? 1.f : 0.f;

    float ox = acc.x*wl0.x + acc.y*wl1.x + acc.z*wl2.x + acc.w*wl3.x;
    float oy = acc.x*wl0.y + acc.y*wl1.y + acc.z*wl2.y + acc.w*wl3.y;
    float oz = acc.x*wl0.z + acc.y*wl1.z + acc.z*wl2.z + acc.w*wl3.z;
    float ow = acc.x*wl0.w + acc.y*wl1.w + acc.z*wl2.w + acc.w*wl3.w;

    float4 v;
    v.x = fmaxf(fmaf(ox, invd, fmaf(bsel, bl4.x, cb.x)), 0.f);
    v.y = fmaxf(fmaf(oy, invd, fmaf(bsel, bl4.y, cb.y)), 0.f);
    v.z = fmaxf(fmaf(oz, invd, fmaf(bsel, bl4.z, cb.z)), 0.f);
    v.w = fmaxf(fmaf(ow, invd, fmaf(bsel, bl4.w, cb.w)), 0.f);

    float s = v.x + v.y + v.z + v.w;
    float q = v.x*v.x + v.y*v.y + v.z*v.z + v.w*v.w;
    float t = v.x*lw.x*pw.x + v.y*lw.y*pw.y + v.z*lw.z*pw.z + v.w*lw.w*pw.w;
    #pragma unroll
    for (int off = 8; off > 0; off >>= 1) {
        s += __shfl_xor_sync(FULL, s, off);
        q += __shfl_xor_sync(FULL, q, off);
        t += __shfl_xor_sync(FULL, t, off);
    }
    if (j == 0) {
        int g = batch[n];
        atomicAdd(&sS[g], t);
        atomicAdd(&sC[g], 1);
        atomicAdd(&sSum, s);
        atomicAdd(&sSq,  q);
    }
    __syncthreads();

    if (tid < N_GRAPHS && sC[tid] != 0) {
        atomicAdd(&g_S[tid], (double)sS[tid]);
        atomicAdd(&g_cnt[tid], sC[tid]);
    }
    if (tid == 0) {
        atomicAdd(&g_sum, (double)sSum);
        atomicAdd(&g_sq,  (double)sSq);
    }
}

// -------- kernel 5: final scalar combine + sigmoid --------
__global__ void k_final(float* __restrict__ out) {
    int t = threadIdx.x;
    double Ntot = (double)N_NODES * HID;
    double mu_d  = g_sum / Ntot;
    double var_d = g_sq / Ntot - mu_d * mu_d;
    float mu  = (float)mu_d;
    float inv = rsqrtf((float)var_d + LN_EPS);

    float cnt = fmaxf((float)g_cnt[t], 1.f);
    float y = inv * ((float)g_S[t] / cnt - mu * g_sW) + g_sB;
    out[t] = 1.f / (1.f + __expf(-y));
}

extern "C" void kernel_launch(void* const* d_in, const int* in_sizes, int n_in,
                              void* d_out, int out_size) {
    const float* x         = (const float*)d_in[0];
    const int*   ei        = (const int*)  d_in[1];
    const int*   batch     = (const int*)  d_in[2];
    const float* W_l       = (const float*)d_in[3];
    const float* b_l       = (const float*)d_in[4];
    const float* W_r       = (const float*)d_in[5];
    const float* b_r       = (const float*)d_in[6];
    const float* att       = (const float*)d_in[7];
    const float* conv_bias = (const float*)d_in[8];
    const float* ln_w      = (const float*)d_in[9];
    const float* ln_b      = (const float*)d_in[10];
    const float* lin_w     = (const float*)d_in[11];
    const float* lin_b     = (const float*)d_in[12];
    float* out = (float*)d_out;

    k_zero<<<512, 256>>>();
    k_const<<<1, 32>>>(W_l, W_r, att, b_l, b_r, ln_w, ln_b, lin_w, lin_b);
    k_pre<<<(N_NODES + 255) / 256, 256>>>(x);
    k_edge<<<N_EDGES / 16, 256>>>(ei, x, W_l, W_r, att, b_l, b_r);   // 2 edges/warp
    k_node<<<N_NODES / 16, 256>>>(W_l, b_l, conv_bias, ln_w, lin_w, batch);
    k_final<<<1, N_GRAPHS>>>(out);
}

// round 5
// speedup vs baseline: 1.5354x; 1.5354x over previous
#include <cuda_runtime.h>
#include <cuda_bf16.h>

#define N_NODES  100000
#define N_EDGES  1600000
#define N_GRAPHS 64
#define HID      64
#define LN_EPS   1e-5f
#define FULL     0xffffffffu
#define EDGE_BLOCKS 1184

typedef unsigned long long u64;

#define FMA2(d,a,b,c)  asm("fma.rn.f32x2 %0, %1, %2, %3;" : "=l"(d) : "l"(a), "l"(b), "l"(c))
#define MUL2(d,a,b)    asm("mul.rn.f32x2 %0, %1, %2;"     : "=l"(d) : "l"(a), "l"(b))
#define PACK2(d,lo,hi) asm("mov.b64 %0, {%1, %2};"        : "=l"(d) : "f"(lo), "f"(hi))
#define UNPACK2(lo,hi,s) asm("mov.b64 {%0, %1}, %2;"      : "=f"(lo), "=f"(hi) : "l"(s))
#define ABS2(d,s)      asm("and.b64 %0, %1, 0x7FFFFFFF7FFFFFFF;" : "=l"(d) : "l"(s))

// -------- persistent device scratch --------
__device__ float4 g_acc[N_NODES];     // sum_e ex * x[src]  (4-dim)
__device__ float  g_den[N_NODES];     // sum_e ex
__device__ float  g_adl[N_NODES];     // att.(x@W_l)
__device__ float  g_ad [N_NODES];     // att.(x@W_r) + att.(b_l+b_r)
__device__ float4 g_wal, g_war;
__device__ float  g_cad;
__device__ float  g_sW, g_sB;
__device__ double g_S[N_GRAPHS];
__device__ int    g_cnt[N_GRAPHS];
__device__ double g_sum, g_sq;

// -------- kernel 0: zero accumulators --------
__global__ void k_zero() {
    int i = blockIdx.x * blockDim.x + threadIdx.x;
    int stride = gridDim.x * blockDim.x;
    for (int t = i; t < N_NODES; t += stride) {
        g_acc[t] = make_float4(0.f, 0.f, 0.f, 0.f);
        g_den[t] = 0.f;
    }
    if (i < N_GRAPHS) { g_S[i] = 0.0; g_cnt[i] = 0; }
    if (i == 0) { g_sum = 0.0; g_sq = 0.0; }
}

// -------- kernel 1: tiny constants (one warp) --------
__global__ void k_const(const float* __restrict__ W_l, const float* __restrict__ W_r,
                        const float* __restrict__ att,
                        const float* __restrict__ b_l, const float* __restrict__ b_r,
                        const float* __restrict__ ln_w, const float* __restrict__ ln_b,
                        const float* __restrict__ lin_w, const float* __restrict__ lin_b) {
    int c = threadIdx.x;
    float a0 = att[c], a1 = att[c + 32];
    float p0 = W_l[0*64+c]*a0 + W_l[0*64+c+32]*a1;
    float p1 = W_l[1*64+c]*a0 + W_l[1*64+c+32]*a1;
    float p2 = W_l[2*64+c]*a0 + W_l[2*64+c+32]*a1;
    float p3 = W_l[3*64+c]*a0 + W_l[3*64+c+32]*a1;
    float r0 = W_r[0*64+c]*a0 + W_r[0*64+c+32]*a1;
    float r1 = W_r[1*64+c]*a0 + W_r[1*64+c+32]*a1;
    float r2 = W_r[2*64+c]*a0 + W_r[2*64+c+32]*a1;
    float r3 = W_r[3*64+c]*a0 + W_r[3*64+c+32]*a1;
    float bb = (b_l[c]+b_r[c])*a0 + (b_l[c+32]+b_r[c+32])*a1;
    float sw = ln_w[c]*lin_w[c] + ln_w[c+32]*lin_w[c+32];
    float sb = ln_b[c]*lin_w[c] + ln_b[c+32]*lin_w[c+32];
    #pragma unroll
    for (int off = 16; off > 0; off >>= 1) {
        p0 += __shfl_xor_sync(FULL, p0, off);
        p1 += __shfl_xor_sync(FULL, p1, off);
        p2 += __shfl_xor_sync(FULL, p2, off);
        p3 += __shfl_xor_sync(FULL, p3, off);
        r0 += __shfl_xor_sync(FULL, r0, off);
        r1 += __shfl_xor_sync(FULL, r1, off);
        r2 += __shfl_xor_sync(FULL, r2, off);
        r3 += __shfl_xor_sync(FULL, r3, off);
        bb += __shfl_xor_sync(FULL, bb, off);
        sw += __shfl_xor_sync(FULL, sw, off);
        sb += __shfl_xor_sync(FULL, sb, off);
    }
    if (c == 0) {
        g_wal = make_float4(p0, p1, p2, p3);
        g_war = make_float4(r0, r1, r2, r3);
        g_cad = bb;
        g_sW = sw;
        g_sB = sb + lin_b[0];
    }
}

// -------- kernel 2: per-node linear attention scalars --------
__global__ void k_pre(const float* __restrict__ x) {
    int n = blockIdx.x * blockDim.x + threadIdx.x;
    if (n >= N_NODES) return;
    float4 wal = g_wal, war = g_war;
    float4 xn = ((const float4*)x)[n];
    g_adl[n] = xn.x*wal.x + xn.y*wal.y + xn.z*wal.z + xn.w*wal.w;
    g_ad [n] = xn.x*war.x + xn.y*war.y + xn.z*war.z + xn.w*war.w + g_cad;
}

// -------- kernel 3: edge-parallel attention, grid-stride, f32x2 packed --------
// warp processes 2 edges per iteration; 16 lanes/edge; lane j owns
// channels [4j,4j+4) as two packed f32x2 pairs. Weights live in registers.
__global__ void __launch_bounds__(256)
k_edge(const int* __restrict__ ei, const float* __restrict__ x,
       const float* __restrict__ W_l, const float* __restrict__ W_r,
       const float* __restrict__ att,
       const float* __restrict__ b_l, const float* __restrict__ b_r) {
    int tid  = blockIdx.x * blockDim.x + threadIdx.x;
    int lane = threadIdx.x & 31;
    int half = lane >> 4;
    int j    = lane & 15;

    const float4* x4  = (const float4*)x;
    const float4* wl4 = (const float4*)W_l;
    const float4* wr4 = (const float4*)W_r;

    u64 wl01[4], wl23[4], wr01[4], wr23[4];
    #pragma unroll
    for (int k = 0; k < 4; k++) {
        float4 t = wl4[16*k + j]; PACK2(wl01[k], t.x, t.y); PACK2(wl23[k], t.z, t.w);
        float4 u = wr4[16*k + j]; PACK2(wr01[k], u.x, u.y); PACK2(wr23[k], u.z, u.w);
    }
    float4 av = ((const float4*)att)[j];
    u64 av01, av23; PACK2(av01, av.x, av.y); PACK2(av23, av.z, av.w);
    float4 bl4 = ((const float4*)b_l)[j];
    float4 br4 = ((const float4*)b_r)[j];
    u64 brl01, brl23;
    PACK2(brl01, bl4.x + br4.x, bl4.y + br4.y);
    PACK2(brl23, bl4.z + br4.z, bl4.w + br4.w);

    int warpId = tid >> 5;
    const int NW = (EDGE_BLOCKS * 256) >> 5;

    #pragma unroll 2
    for (int pair = warpId; pair < N_EDGES / 2; pair += NW) {
        int e   = pair * 2 + half;
        int src = ei[e];
        int dst = ei[N_EDGES + e];
        float4 xs = x4[src];
        float4 xd = x4[dst];

        u64 h01 = brl01, h23 = brl23, m;
        PACK2(m, xs.x, xs.x); FMA2(h01, m, wl01[0], h01); FMA2(h23, m, wl23[0], h23);
        PACK2(m, xs.y, xs.y); FMA2(h01, m, wl01[1], h01); FMA2(h23, m, wl23[1], h23);
        PACK2(m, xs.z, xs.z); FMA2(h01, m, wl01[2], h01); FMA2(h23, m, wl23[2], h23);
        PACK2(m, xs.w, xs.w); FMA2(h01, m, wl01[3], h01); FMA2(h23, m, wl23[3], h23);
        PACK2(m, xd.x, xd.x); FMA2(h01, m, wr01[0], h01); FMA2(h23, m, wr23[0], h23);
        PACK2(m, xd.y, xd.y); FMA2(h01, m, wr01[1], h01); FMA2(h23, m, wr23[1], h23);
        PACK2(m, xd.z, xd.z); FMA2(h01, m, wr01[2], h01); FMA2(h23, m, wr23[2], h23);
        PACK2(m, xd.w, xd.w); FMA2(h01, m, wr01[3], h01); FMA2(h23, m, wr23[3], h23);

        ABS2(h01, h01); ABS2(h23, h23);
        u64 d2; MUL2(d2, av01, h01); FMA2(d2, av23, h23, d2);
        float lo, hi; UNPACK2(lo, hi, d2);
        float eabs = lo + hi;
        eabs += __shfl_xor_sync(FULL, eabs, 8);
        eabs += __shfl_xor_sync(FULL, eabs, 4);
        eabs += __shfl_xor_sync(FULL, eabs, 2);
        eabs += __shfl_xor_sync(FULL, eabs, 1);

        if (j == 0) {
            float elin = g_adl[src] + g_ad[dst];
            float ex = __expf(fmaf(0.4f, eabs, 0.6f * elin));  // softmax shift cancels
            float* accp = (float*)&g_acc[dst];
            asm volatile("red.global.add.v4.f32 [%0], {%1,%2,%3,%4};"
                         :: "l"(accp), "f"(ex*xs.x), "f"(ex*xs.y), "f"(ex*xs.z), "f"(ex*xs.w)
                         : "memory");
            asm volatile("red.global.add.f32 [%0], %1;"
                         :: "l"(&g_den[dst]), "f"(ex) : "memory");
        }
    }
}

// -------- kernel 4: node finalize + LN/pool stats --------
// warp = 2 nodes; 16 lanes per node; lane j owns channels [4j, 4j+4)
__global__ void k_node(const float* __restrict__ W_l, const float* __restrict__ b_l,
                       const float* __restrict__ conv_bias,
                       const float* __restrict__ ln_w, const float* __restrict__ lin_w,
                       const int* __restrict__ batch) {
    __shared__ float sS[N_GRAPHS];
    __shared__ int   sC[N_GRAPHS];
    __shared__ float sSum, sSq;
    int tid = threadIdx.x;
    if (tid < N_GRAPHS) { sS[tid] = 0.f; sC[tid] = 0; }
    if (tid == 0) { sSum = 0.f; sSq = 0.f; }
    __syncthreads();

    int lane = tid & 31;
    int half = lane >> 4;
    int j    = lane & 15;
    int n = ((blockIdx.x * blockDim.x + tid) >> 5) * 2 + half;

    const float4* wl4 = (const float4*)W_l;
    float4 wl0 = wl4[j], wl1 = wl4[16 + j], wl2 = wl4[32 + j], wl3 = wl4[48 + j];
    float4 bl4 = ((const float4*)b_l)[j];
    float4 cb  = ((const float4*)conv_bias)[j];
    float4 lw  = ((const float4*)ln_w)[j];
    float4 pw  = ((const float4*)lin_w)[j];

    float4 acc = g_acc[n];
    float  den = g_den[n];
    float invd = den > 0.f ? 1.f / den : 0.f;
    float bsel = den > 0.f ? 1.f : 0.f;

    float ox = acc.x*wl0.x + acc.y*wl1.x + acc.z*wl2.x + acc.w*wl3.x;
    float oy = acc.x*wl0.y + acc.y*wl1.y + acc.z*wl2.y + acc.w*wl3.y;
    float oz = acc.x*wl0.z + acc.y*wl1.z + acc.z*wl2.z + acc.w*wl3.z;
    float ow = acc.x*wl0.w + acc.y*wl1.w + acc.z*wl2.w + acc.w*wl3.w;

    float4 v;
    v.x = fmaxf(fmaf(ox, invd, fmaf(bsel, bl4.x, cb.x)), 0.f);
    v.y = fmaxf(fmaf(oy, invd, fmaf(bsel, bl4.y, cb.y)), 0.f);
    v.z = fmaxf(fmaf(oz, invd, fmaf(bsel, bl4.z, cb.z)), 0.f);
    v.w = fmaxf(fmaf(ow, invd, fmaf(bsel, bl4.w, cb.w)), 0.f);

    float s = v.x + v.y + v.z + v.w;
    float q = v.x*v.x + v.y*v.y + v.z*v.z + v.w*v.w;
    float t = v.x*lw.x*pw.x + v.y*lw.y*pw.y + v.z*lw.z*pw.z + v.w*lw.w*pw.w;
    #pragma unroll
    for (int off = 8; off > 0; off >>= 1) {
        s += __shfl_xor_sync(FULL, s, off);
        q += __shfl_xor_sync(FULL, q, off);
        t += __shfl_xor_sync(FULL, t, off);
    }
    if (j == 0) {
        int g = batch[n];
        atomicAdd(&sS[g], t);
        atomicAdd(&sC[g], 1);
        atomicAdd(&sSum, s);
        atomicAdd(&sSq,  q);
    }
    __syncthreads();

    if (tid < N_GRAPHS && sC[tid] != 0) {
        atomicAdd(&g_S[tid], (double)sS[tid]);
        atomicAdd(&g_cnt[tid], sC[tid]);
    }
    if (tid == 0) {
        atomicAdd(&g_sum, (double)sSum);
        atomicAdd(&g_sq,  (double)sSq);
    }
}

// -------- kernel 5: final scalar combine + sigmoid --------
__global__ void k_final(float* __restrict__ out) {
    int t = threadIdx.x;
    double Ntot = (double)N_NODES * HID;
    double mu_d  = g_sum / Ntot;
    double var_d = g_sq / Ntot - mu_d * mu_d;
    float mu  = (float)mu_d;
    float inv = rsqrtf((float)var_d + LN_EPS);

    float cnt = fmaxf((float)g_cnt[t], 1.f);
    float y = inv * ((float)g_S[t] / cnt - mu * g_sW) + g_sB;
    out[t] = 1.f / (1.f + __expf(-y));
}

extern "C" void kernel_launch(void* const* d_in, const int* in_sizes, int n_in,
                              void* d_out, int out_size) {
    const float* x         = (const float*)d_in[0];
    const int*   ei        = (const int*)  d_in[1];
    const int*   batch     = (const int*)  d_in[2];
    const float* W_l       = (const float*)d_in[3];
    const float* b_l       = (const float*)d_in[4];
    const float* W_r       = (const float*)d_in[5];
    const float* b_r       = (const float*)d_in[6];
    const float* att       = (const float*)d_in[7];
    const float* conv_bias = (const float*)d_in[8];
    const float* ln_w      = (const float*)d_in[9];
    const float* ln_b      = (const float*)d_in[10];
    const float* lin_w     = (const float*)d_in[11];
    const float* lin_b     = (const float*)d_in[12];
    float* out = (float*)d_out;

    k_zero<<<512, 256>>>();
    k_const<<<1, 32>>>(W_l, W_r, att, b_l, b_r, ln_w, ln_b, lin_w, lin_b);
    k_pre<<<(N_NODES + 255) / 256, 256>>>(x);
    k_edge<<<EDGE_BLOCKS, 256>>>(ei, x, W_l, W_r, att, b_l, b_r);
    k_node<<<N_NODES / 16, 256>>>(W_l, b_l, conv_bias, ln_w, lin_w, batch);
    k_final<<<1, N_GRAPHS>>>(out);
}

// round 6
// speedup vs baseline: 1.8974x; 1.2358x over previous
#include <cuda_runtime.h>
#include <cuda_fp16.h>
#include <cuda_bf16.h>

#define N_NODES  100000
#define N_EDGES  1600000
#define N_GRAPHS 64
#define HID      64
#define LN_EPS   1e-5f
#define FULL     0xffffffffu
#define EDGE_BLOCKS 1184

// -------- persistent device scratch --------
__device__ uint2  g_xl16[N_NODES * 16];   // att ⊙ (x@W_l), fp16, 4 ch per uint2
__device__ uint2  g_xr16[N_NODES * 16];   // att ⊙ (x@W_r + b_l + b_r), fp16
__device__ float4 g_acc[N_NODES];         // sum_e ex * x[src]  (4-dim)
__device__ float  g_den[N_NODES];         // sum_e ex
__device__ float  g_adl[N_NODES];         // att.(x@W_l)
__device__ float  g_ad [N_NODES];         // att.(x@W_r) + att.(b_l+b_r)
__device__ float4 g_wal, g_war;
__device__ float  g_cad;
__device__ float  g_sW, g_sB;
__device__ double g_S[N_GRAPHS];
__device__ int    g_cnt[N_GRAPHS];
__device__ double g_sum, g_sq;

// -------- kernel 0: zero accumulators --------
__global__ void k_zero() {
    int i = blockIdx.x * blockDim.x + threadIdx.x;
    int stride = gridDim.x * blockDim.x;
    for (int t = i; t < N_NODES; t += stride) {
        g_acc[t] = make_float4(0.f, 0.f, 0.f, 0.f);
        g_den[t] = 0.f;
    }
    if (i < N_GRAPHS) { g_S[i] = 0.0; g_cnt[i] = 0; }
    if (i == 0) { g_sum = 0.0; g_sq = 0.0; }
}

// -------- kernel 1: tiny constants (one warp) --------
__global__ void k_const(const float* __restrict__ W_l, const float* __restrict__ W_r,
                        const float* __restrict__ att,
                        const float* __restrict__ b_l, const float* __restrict__ b_r,
                        const float* __restrict__ ln_w, const float* __restrict__ ln_b,
                        const float* __restrict__ lin_w, const float* __restrict__ lin_b) {
    int c = threadIdx.x;
    float a0 = att[c], a1 = att[c + 32];
    float p0 = W_l[0*64+c]*a0 + W_l[0*64+c+32]*a1;
    float p1 = W_l[1*64+c]*a0 + W_l[1*64+c+32]*a1;
    float p2 = W_l[2*64+c]*a0 + W_l[2*64+c+32]*a1;
    float p3 = W_l[3*64+c]*a0 + W_l[3*64+c+32]*a1;
    float r0 = W_r[0*64+c]*a0 + W_r[0*64+c+32]*a1;
    float r1 = W_r[1*64+c]*a0 + W_r[1*64+c+32]*a1;
    float r2 = W_r[2*64+c]*a0 + W_r[2*64+c+32]*a1;
    float r3 = W_r[3*64+c]*a0 + W_r[3*64+c+32]*a1;
    float bb = (b_l[c]+b_r[c])*a0 + (b_l[c+32]+b_r[c+32])*a1;
    float sw = ln_w[c]*lin_w[c] + ln_w[c+32]*lin_w[c+32];
    float sb = ln_b[c]*lin_w[c] + ln_b[c+32]*lin_w[c+32];
    #pragma unroll
    for (int off = 16; off > 0; off >>= 1) {
        p0 += __shfl_xor_sync(FULL, p0, off);
        p1 += __shfl_xor_sync(FULL, p1, off);
        p2 += __shfl_xor_sync(FULL, p2, off);
        p3 += __shfl_xor_sync(FULL, p3, off);
        r0 += __shfl_xor_sync(FULL, r0, off);
        r1 += __shfl_xor_sync(FULL, r1, off);
        r2 += __shfl_xor_sync(FULL, r2, off);
        r3 += __shfl_xor_sync(FULL, r3, off);
        bb += __shfl_xor_sync(FULL, bb, off);
        sw += __shfl_xor_sync(FULL, sw, off);
        sb += __shfl_xor_sync(FULL, sb, off);
    }
    if (c == 0) {
        g_wal = make_float4(p0, p1, p2, p3);
        g_war = make_float4(r0, r1, r2, r3);
        g_cad = bb;
        g_sW = sw;
        g_sB = sb + lin_b[0];
    }
}

// -------- kernel 2: node projections -> fp16 (att-folded) + linear scalars --------
// warp = 2 nodes; 16 lanes per node; lane j owns channels [4j, 4j+4)
__global__ void k_prehalf(const float* __restrict__ x,
                          const float* __restrict__ W_l, const float* __restrict__ W_r,
                          const float* __restrict__ att,
                          const float* __restrict__ b_l, const float* __restrict__ b_r) {
    int tid  = blockIdx.x * blockDim.x + threadIdx.x;
    int lane = threadIdx.x & 31;
    int half = lane >> 4;
    int j    = lane & 15;
    int n = (tid >> 5) * 2 + half;

    const float4* x4  = (const float4*)x;
    const float4* wl4 = (const float4*)W_l;
    const float4* wr4 = (const float4*)W_r;
    float4 wl0 = wl4[j], wl1 = wl4[16 + j], wl2 = wl4[32 + j], wl3 = wl4[48 + j];
    float4 wr0 = wr4[j], wr1 = wr4[16 + j], wr2 = wr4[32 + j], wr3 = wr4[48 + j];
    float4 av  = ((const float4*)att)[j];
    float4 bl4 = ((const float4*)b_l)[j];
    float4 br4 = ((const float4*)b_r)[j];

    float4 xn = x4[n];
    float lx = xn.x*wl0.x + xn.y*wl1.x + xn.z*wl2.x + xn.w*wl3.x;
    float ly = xn.x*wl0.y + xn.y*wl1.y + xn.z*wl2.y + xn.w*wl3.y;
    float lz = xn.x*wl0.z + xn.y*wl1.z + xn.z*wl2.z + xn.w*wl3.z;
    float lw = xn.x*wl0.w + xn.y*wl1.w + xn.z*wl2.w + xn.w*wl3.w;
    float rx = bl4.x + br4.x + xn.x*wr0.x + xn.y*wr1.x + xn.z*wr2.x + xn.w*wr3.x;
    float ry = bl4.y + br4.y + xn.x*wr0.y + xn.y*wr1.y + xn.z*wr2.y + xn.w*wr3.y;
    float rz = bl4.z + br4.z + xn.x*wr0.z + xn.y*wr1.z + xn.z*wr2.z + xn.w*wr3.z;
    float rw = bl4.w + br4.w + xn.x*wr0.w + xn.y*wr1.w + xn.z*wr2.w + xn.w*wr3.w;

    // fold att in (sign handled in edge kernel)
    half2 l01 = __floats2half2_rn(lx*av.x, ly*av.y);
    half2 l23 = __floats2half2_rn(lz*av.z, lw*av.w);
    half2 r01 = __floats2half2_rn(rx*av.x, ry*av.y);
    half2 r23 = __floats2half2_rn(rz*av.z, rw*av.w);
    uint2 ul, ur;
    ul.x = *(unsigned*)&l01; ul.y = *(unsigned*)&l23;
    ur.x = *(unsigned*)&r01; ur.y = *(unsigned*)&r23;
    g_xl16[n * 16 + j] = ul;
    g_xr16[n * 16 + j] = ur;

    if (j == 0) {
        float4 wal = g_wal, war = g_war;
        g_adl[n] = xn.x*wal.x + xn.y*wal.y + xn.z*wal.z + xn.w*wal.w;
        g_ad [n] = xn.x*war.x + xn.y*war.y + xn.z*war.z + xn.w*war.w + g_cad;
    }
}

// -------- kernel 3: edge-parallel attention, fp16 gathers --------
// warp = 2 edges/iter; 16 lanes per edge; lane j owns channels [4j, 4j+4)
__global__ void __launch_bounds__(256)
k_edge(const int* __restrict__ ei, const float* __restrict__ x,
       const float* __restrict__ att) {
    int tid  = blockIdx.x * blockDim.x + threadIdx.x;
    int lane = threadIdx.x & 31;
    int half = lane >> 4;
    int j    = lane & 15;

    const float4* x4 = (const float4*)x;
    float4 av = ((const float4*)att)[j];
    // sign-fold masks: |h'| then flip sign where att<0
    unsigned m01 = (av.x < 0.f ? 0x8000u : 0u) | (av.y < 0.f ? 0x80000000u : 0u);
    unsigned m23 = (av.z < 0.f ? 0x8000u : 0u) | (av.w < 0.f ? 0x80000000u : 0u);

    int warpId = tid >> 5;
    const int NW = (EDGE_BLOCKS * 256) >> 5;

    for (int pair = warpId; pair < N_EDGES / 2; pair += NW) {
        int e   = pair * 2 + half;
        int src = ei[e];
        int dst = ei[N_EDGES + e];

        uint2 A = g_xl16[src * 16 + j];
        uint2 B = g_xr16[dst * 16 + j];
        float4 xs   = x4[src];
        float  elin = g_adl[src] + g_ad[dst];

        unsigned h0, h1;
        asm("add.rn.f16x2 %0, %1, %2;" : "=r"(h0) : "r"(A.x), "r"(B.x));
        asm("add.rn.f16x2 %0, %1, %2;" : "=r"(h1) : "r"(A.y), "r"(B.y));
        h0 = (h0 & 0x7FFF7FFFu) ^ m01;      // sgn(att)*|att*h|
        h1 = (h1 & 0x7FFF7FFFu) ^ m23;
        float2 f0 = __half22float2(*(half2*)&h0);
        float2 f1 = __half22float2(*(half2*)&h1);
        float eabs = (f0.x + f0.y) + (f1.x + f1.y);

        eabs += __shfl_xor_sync(FULL, eabs, 8);
        eabs += __shfl_xor_sync(FULL, eabs, 4);
        eabs += __shfl_xor_sync(FULL, eabs, 2);
        eabs += __shfl_xor_sync(FULL, eabs, 1);

        if (j == 0) {
            float ex = __expf(fmaf(0.4f, eabs, 0.6f * elin));  // softmax shift cancels
            float* accp = (float*)&g_acc[dst];
            asm volatile("red.global.add.v4.f32 [%0], {%1,%2,%3,%4};"
                         :: "l"(accp), "f"(ex*xs.x), "f"(ex*xs.y), "f"(ex*xs.z), "f"(ex*xs.w)
                         : "memory");
            asm volatile("red.global.add.f32 [%0], %1;"
                         :: "l"(&g_den[dst]), "f"(ex) : "memory");
        }
    }
}

// -------- kernel 4: node finalize + LN/pool stats --------
// warp = 2 nodes; 16 lanes per node; lane j owns channels [4j, 4j+4)
__global__ void k_node(const float* __restrict__ W_l, const float* __restrict__ b_l,
                       const float* __restrict__ conv_bias,
                       const float* __restrict__ ln_w, const float* __restrict__ lin_w,
                       const int* __restrict__ batch) {
    __shared__ float sS[N_GRAPHS];
    __shared__ int   sC[N_GRAPHS];
    __shared__ float sSum, sSq;
    int tid = threadIdx.x;
    if (tid < N_GRAPHS) { sS[tid] = 0.f; sC[tid] = 0; }
    if (tid == 0) { sSum = 0.f; sSq = 0.f; }
    __syncthreads();

    int lane = tid & 31;
    int half = lane >> 4;
    int j    = lane & 15;
    int n = ((blockIdx.x * blockDim.x + tid) >> 5) * 2 + half;

    const float4* wl4 = (const float4*)W_l;
    float4 wl0 = wl4[j], wl1 = wl4[16 + j], wl2 = wl4[32 + j], wl3 = wl4[48 + j];
    float4 bl4 = ((const float4*)b_l)[j];
    float4 cb  = ((const float4*)conv_bias)[j];
    float4 lw  = ((const float4*)ln_w)[j];
    float4 pw  = ((const float4*)lin_w)[j];

    float4 acc = g_acc[n];
    float  den = g_den[n];
    float invd = den > 0.f ? 1.f / den : 0.f;
    float bsel = den > 0.f ? 1.f : 0.f;

    float ox = acc.x*wl0.x + acc.y*wl1.x + acc.z*wl2.x + acc.w*wl3.x;
    float oy = acc.x*wl0.y + acc.y*wl1.y + acc.z*wl2.y + acc.w*wl3.y;
    float oz = acc.x*wl0.z + acc.y*wl1.z + acc.z*wl2.z + acc.w*wl3.z;
    float ow = acc.x*wl0.w + acc.y*wl1.w + acc.z*wl2.w + acc.w*wl3.w;

    float4 v;
    v.x = fmaxf(fmaf(ox, invd, fmaf(bsel, bl4.x, cb.x)), 0.f);
    v.y = fmaxf(fmaf(oy, invd, fmaf(bsel, bl4.y, cb.y)), 0.f);
    v.z = fmaxf(fmaf(oz, invd, fmaf(bsel, bl4.z, cb.z)), 0.f);
    v.w = fmaxf(fmaf(ow, invd, fmaf(bsel, bl4.w, cb.w)), 0.f);

    float s = v.x + v.y + v.z + v.w;
    float q = v.x*v.x + v.y*v.y + v.z*v.z + v.w*v.w;
    float t = v.x*lw.x*pw.x + v.y*lw.y*pw.y + v.z*lw.z*pw.z + v.w*lw.w*pw.w;
    #pragma unroll
    for (int off = 8; off > 0; off >>= 1) {
        s += __shfl_xor_sync(FULL, s, off);
        q += __shfl_xor_sync(FULL, q, off);
        t += __shfl_xor_sync(FULL, t, off);
    }
    if (j == 0) {
        int g = batch[n];
        atomicAdd(&sS[g], t);
        atomicAdd(&sC[g], 1);
        atomicAdd(&sSum, s);
        atomicAdd(&sSq,  q);
    }
    __syncthreads();

    if (tid < N_GRAPHS && sC[tid] != 0) {
        atomicAdd(&g_S[tid], (double)sS[tid]);
        atomicAdd(&g_cnt[tid], sC[tid]);
    }
    if (tid == 0) {
        atomicAdd(&g_sum, (double)sSum);
        atomicAdd(&g_sq,  (double)sSq);
    }
}

// -------- kernel 5: final scalar combine + sigmoid --------
__global__ void k_final(float* __restrict__ out) {
    int t = threadIdx.x;
    double Ntot = (double)N_NODES * HID;
    double mu_d  = g_sum / Ntot;
    double var_d = g_sq / Ntot - mu_d * mu_d;
    float mu  = (float)mu_d;
    float inv = rsqrtf((float)var_d + LN_EPS);

    float cnt = fmaxf((float)g_cnt[t], 1.f);
    float y = inv * ((float)g_S[t] / cnt - mu * g_sW) + g_sB;
    out[t] = 1.f / (1.f + __expf(-y));
}

extern "C" void kernel_launch(void* const* d_in, const int* in_sizes, int n_in,
                              void* d_out, int out_size) {
    const float* x         = (const float*)d_in[0];
    const int*   ei        = (const int*)  d_in[1];
    const int*   batch     = (const int*)  d_in[2];
    const float* W_l       = (const float*)d_in[3];
    const float* b_l       = (const float*)d_in[4];
    const float* W_r       = (const float*)d_in[5];
    const float* b_r       = (const float*)d_in[6];
    const float* att       = (const float*)d_in[7];
    const float* conv_bias = (const float*)d_in[8];
    const float* ln_w      = (const float*)d_in[9];
    const float* ln_b      = (const float*)d_in[10];
    const float* lin_w     = (const float*)d_in[11];
    const float* lin_b     = (const float*)d_in[12];
    float* out = (float*)d_out;

    k_zero<<<512, 256>>>();
    k_const<<<1, 32>>>(W_l, W_r, att, b_l, b_r, ln_w, ln_b, lin_w, lin_b);
    k_prehalf<<<N_NODES / 16, 256>>>(x, W_l, W_r, att, b_l, b_r);
    k_edge<<<EDGE_BLOCKS, 256>>>(ei, x, att);
    k_node<<<N_NODES / 16, 256>>>(W_l, b_l, conv_bias, ln_w, lin_w, batch);
    k_final<<<1, N_GRAPHS>>>(out);
}

// round 7
// speedup vs baseline: 2.5355x; 1.3363x over previous
#include <cuda_runtime.h>
#include <cuda_fp16.h>
#include <cuda_bf16.h>

#define N_NODES  100000
#define N_EDGES  1600000
#define N_GRAPHS 64
#define HID      64
#define LN_EPS   1e-5f
#define FULL     0xffffffffu
#define EDGE_BLOCKS 1184

// -------- persistent device scratch --------
__device__ uint4  g_xl16[N_NODES * 8];    // att ⊙ (x@W_l), fp16, 8 ch per uint4
__device__ uint4  g_xr16[N_NODES * 8];    // att ⊙ (x@W_r + b_l + b_r), fp16
__device__ float4 g_xw[N_NODES];          // exp(0.6*adl[n]) * x[n]
__device__ float  g_w [N_NODES];          // exp(0.6*adl[n])
__device__ float4 g_acc[N_NODES];         // sum_e t * xw[src]  (= sum ex * x[src])
__device__ float  g_den[N_NODES];         // sum_e ex
__device__ float4 g_wal;                  // W_l^T att
__device__ float  g_sW, g_sB;
__device__ double g_S[N_GRAPHS];
__device__ int    g_cnt[N_GRAPHS];
__device__ double g_sum, g_sq;

// -------- kernel 0: zero accumulators --------
__global__ void k_zero() {
    int i = blockIdx.x * blockDim.x + threadIdx.x;
    int stride = gridDim.x * blockDim.x;
    for (int t = i; t < N_NODES; t += stride) {
        g_acc[t] = make_float4(0.f, 0.f, 0.f, 0.f);
        g_den[t] = 0.f;
    }
    if (i < N_GRAPHS) { g_S[i] = 0.0; g_cnt[i] = 0; }
    if (i == 0) { g_sum = 0.0; g_sq = 0.0; }
}

// -------- kernel 1: tiny constants (one warp) --------
__global__ void k_const(const float* __restrict__ W_l, const float* __restrict__ att,
                        const float* __restrict__ ln_w, const float* __restrict__ ln_b,
                        const float* __restrict__ lin_w, const float* __restrict__ lin_b) {
    int c = threadIdx.x;
    float a0 = att[c], a1 = att[c + 32];
    float p0 = W_l[0*64+c]*a0 + W_l[0*64+c+32]*a1;
    float p1 = W_l[1*64+c]*a0 + W_l[1*64+c+32]*a1;
    float p2 = W_l[2*64+c]*a0 + W_l[2*64+c+32]*a1;
    float p3 = W_l[3*64+c]*a0 + W_l[3*64+c+32]*a1;
    float sw = ln_w[c]*lin_w[c] + ln_w[c+32]*lin_w[c+32];
    float sb = ln_b[c]*lin_w[c] + ln_b[c+32]*lin_w[c+32];
    #pragma unroll
    for (int off = 16; off > 0; off >>= 1) {
        p0 += __shfl_xor_sync(FULL, p0, off);
        p1 += __shfl_xor_sync(FULL, p1, off);
        p2 += __shfl_xor_sync(FULL, p2, off);
        p3 += __shfl_xor_sync(FULL, p3, off);
        sw += __shfl_xor_sync(FULL, sw, off);
        sb += __shfl_xor_sync(FULL, sb, off);
    }
    if (c == 0) {
        g_wal = make_float4(p0, p1, p2, p3);
        g_sW = sw;
        g_sB = sb + lin_b[0];
    }
}

// -------- kernel 2: node projections -> fp16 (att-folded) + src weights --------
// warp = 2 nodes; 16 lanes per node; lane j owns channels [4j, 4j+4)
__global__ void k_prehalf(const float* __restrict__ x,
                          const float* __restrict__ W_l, const float* __restrict__ W_r,
                          const float* __restrict__ att,
                          const float* __restrict__ b_l, const float* __restrict__ b_r) {
    int tid  = blockIdx.x * blockDim.x + threadIdx.x;
    int lane = threadIdx.x & 31;
    int half = lane >> 4;
    int j    = lane & 15;
    int n = (tid >> 5) * 2 + half;

    const float4* x4  = (const float4*)x;
    const float4* wl4 = (const float4*)W_l;
    const float4* wr4 = (const float4*)W_r;
    float4 wl0 = wl4[j], wl1 = wl4[16 + j], wl2 = wl4[32 + j], wl3 = wl4[48 + j];
    float4 wr0 = wr4[j], wr1 = wr4[16 + j], wr2 = wr4[32 + j], wr3 = wr4[48 + j];
    float4 av  = ((const float4*)att)[j];
    float4 bl4 = ((const float4*)b_l)[j];
    float4 br4 = ((const float4*)b_r)[j];

    float4 xn = x4[n];
    float lx = xn.x*wl0.x + xn.y*wl1.x + xn.z*wl2.x + xn.w*wl3.x;
    float ly = xn.x*wl0.y + xn.y*wl1.y + xn.z*wl2.y + xn.w*wl3.y;
    float lz = xn.x*wl0.z + xn.y*wl1.z + xn.z*wl2.z + xn.w*wl3.z;
    float lw = xn.x*wl0.w + xn.y*wl1.w + xn.z*wl2.w + xn.w*wl3.w;
    float rx = bl4.x + br4.x + xn.x*wr0.x + xn.y*wr1.x + xn.z*wr2.x + xn.w*wr3.x;
    float ry = bl4.y + br4.y + xn.x*wr0.y + xn.y*wr1.y + xn.z*wr2.y + xn.w*wr3.y;
    float rz = bl4.z + br4.z + xn.x*wr0.z + xn.y*wr1.z + xn.z*wr2.z + xn.w*wr3.z;
    float rw = bl4.w + br4.w + xn.x*wr0.w + xn.y*wr1.w + xn.z*wr2.w + xn.w*wr3.w;

    // fold att in (sign handled in edge kernel)
    half2 l01 = __floats2half2_rn(lx*av.x, ly*av.y);
    half2 l23 = __floats2half2_rn(lz*av.z, lw*av.w);
    half2 r01 = __floats2half2_rn(rx*av.x, ry*av.y);
    half2 r23 = __floats2half2_rn(rz*av.z, rw*av.w);
    uint2* xl2 = (uint2*)g_xl16;
    uint2* xr2 = (uint2*)g_xr16;
    uint2 ul, ur;
    ul.x = *(unsigned*)&l01; ul.y = *(unsigned*)&l23;
    ur.x = *(unsigned*)&r01; ur.y = *(unsigned*)&r23;
    xl2[n * 16 + j] = ul;
    xr2[n * 16 + j] = ur;

    if (j == 0) {
        float4 wal = g_wal;
        float adl = xn.x*wal.x + xn.y*wal.y + xn.z*wal.z + xn.w*wal.w;
        float w = __expf(0.6f * adl);   // dst-side linear term cancels in softmax
        g_w[n] = w;
        g_xw[n] = make_float4(w*xn.x, w*xn.y, w*xn.z, w*xn.w);
    }
}

// -------- kernel 3: edge-parallel attention, 8 lanes/edge, 4 edges/warp --------
// lane: sub = lane>>3 selects edge, k = lane&7 owns channels [8k, 8k+8)
__global__ void __launch_bounds__(256)
k_edge(const int* __restrict__ ei, const float* __restrict__ att) {
    int tid  = blockIdx.x * blockDim.x + threadIdx.x;
    int lane = threadIdx.x & 31;
    int sub  = lane >> 3;
    int k    = lane & 7;

    // sign-fold masks for this lane's 8 channels
    float4 a0 = ((const float4*)att)[2*k];
    float4 a1 = ((const float4*)att)[2*k + 1];
    unsigned m0 = (a0.x < 0.f ? 0x8000u : 0u) | (a0.y < 0.f ? 0x80000000u : 0u);
    unsigned m1 = (a0.z < 0.f ? 0x8000u : 0u) | (a0.w < 0.f ? 0x80000000u : 0u);
    unsigned m2 = (a1.x < 0.f ? 0x8000u : 0u) | (a1.y < 0.f ? 0x80000000u : 0u);
    unsigned m3 = (a1.z < 0.f ? 0x8000u : 0u) | (a1.w < 0.f ? 0x80000000u : 0u);

    int warpId = tid >> 5;
    const int NW = (EDGE_BLOCKS * 256) >> 5;
    const int NQ = N_EDGES / 4;

    for (int quad = warpId; quad < NQ; quad += NW) {
        int e   = quad * 4 + sub;
        int src = ei[e];
        int dst = ei[N_EDGES + e];

        uint4 A = g_xl16[src * 8 + k];
        uint4 B = g_xr16[dst * 8 + k];

        unsigned h0, h1, h2, h3;
        asm("add.rn.f16x2 %0, %1, %2;" : "=r"(h0) : "r"(A.x), "r"(B.x));
        asm("add.rn.f16x2 %0, %1, %2;" : "=r"(h1) : "r"(A.y), "r"(B.y));
        asm("add.rn.f16x2 %0, %1, %2;" : "=r"(h2) : "r"(A.z), "r"(B.z));
        asm("add.rn.f16x2 %0, %1, %2;" : "=r"(h3) : "r"(A.w), "r"(B.w));
        h0 = (h0 & 0x7FFF7FFFu) ^ m0;      // sgn(att)*|att*h| per fp16 pair
        h1 = (h1 & 0x7FFF7FFFu) ^ m1;
        h2 = (h2 & 0x7FFF7FFFu) ^ m2;
        h3 = (h3 & 0x7FFF7FFFu) ^ m3;
        // pairwise fp16 adds (2 terms each), then fp32 accumulate
        unsigned s0, s1;
        asm("add.rn.f16x2 %0, %1, %2;" : "=r"(s0) : "r"(h0), "r"(h1));
        asm("add.rn.f16x2 %0, %1, %2;" : "=r"(s1) : "r"(h2), "r"(h3));
        float2 f0 = __half22float2(*(half2*)&s0);
        float2 f1 = __half22float2(*(half2*)&s1);
        float eabs = (f0.x + f0.y) + (f1.x + f1.y);

        eabs += __shfl_xor_sync(FULL, eabs, 4);
        eabs += __shfl_xor_sync(FULL, eabs, 2);
        eabs += __shfl_xor_sync(FULL, eabs, 1);

        if (k == 0) {
            float4 xw = g_xw[src];
            float  w  = g_w[src];
            float t  = __expf(0.4f * eabs);
            float ex = t * w;                       // full (shift-free) ex
            float* accp = (float*)&g_acc[dst];
            asm volatile("red.global.add.v4.f32 [%0], {%1,%2,%3,%4};"
                         :: "l"(accp), "f"(t*xw.x), "f"(t*xw.y), "f"(t*xw.z), "f"(t*xw.w)
                         : "memory");
            asm volatile("red.global.add.f32 [%0], %1;"
                         :: "l"(&g_den[dst]), "f"(ex) : "memory");
        }
    }
}

// -------- kernel 4: node finalize + LN/pool stats --------
// warp = 2 nodes; 16 lanes per node; lane j owns channels [4j, 4j+4)
__global__ void k_node(const float* __restrict__ W_l, const float* __restrict__ b_l,
                       const float* __restrict__ conv_bias,
                       const float* __restrict__ ln_w, const float* __restrict__ lin_w,
                       const int* __restrict__ batch) {
    __shared__ float sS[N_GRAPHS];
    __shared__ int   sC[N_GRAPHS];
    __shared__ float sSum, sSq;
    int tid = threadIdx.x;
    if (tid < N_GRAPHS) { sS[tid] = 0.f; sC[tid] = 0; }
    if (tid == 0) { sSum = 0.f; sSq = 0.f; }
    __syncthreads();

    int lane = tid & 31;
    int half = lane >> 4;
    int j    = lane & 15;
    int n = ((blockIdx.x * blockDim.x + tid) >> 5) * 2 + half;

    const float4* wl4 = (const float4*)W_l;
    float4 wl0 = wl4[j], wl1 = wl4[16 + j], wl2 = wl4[32 + j], wl3 = wl4[48 + j];
    float4 bl4 = ((const float4*)b_l)[j];
    float4 cb  = ((const float4*)conv_bias)[j];
    float4 lw  = ((const float4*)ln_w)[j];
    float4 pw  = ((const float4*)lin_w)[j];

    float4 acc = g_acc[n];
    float  den = g_den[n];
    float invd = den > 0.f ? 1.f / den : 0.f;
    float bsel = den > 0.f ? 1.f : 0.f;

    float ox = acc.x*wl0.x + acc.y*wl1.x + acc.z*wl2.x + acc.w*wl3.x;
    float oy = acc.x*wl0.y + acc.y*wl1.y + acc.z*wl2.y + acc.w*wl3.y;
    float oz = acc.x*wl0.z + acc.y*wl1.z + acc.z*wl2.z + acc.w*wl3.z;
    float ow = acc.x*wl0.w + acc.y*wl1.w + acc.z*wl2.w + acc.w*wl3.w;

    float4 v;
    v.x = fmaxf(fmaf(ox, invd, fmaf(bsel, bl4.x, cb.x)), 0.f);
    v.y = fmaxf(fmaf(oy, invd, fmaf(bsel, bl4.y, cb.y)), 0.f);
    v.z = fmaxf(fmaf(oz, invd, fmaf(bsel, bl4.z, cb.z)), 0.f);
    v.w = fmaxf(fmaf(ow, invd, fmaf(bsel, bl4.w, cb.w)), 0.f);

    float s = v.x + v.y + v.z + v.w;
    float q = v.x*v.x + v.y*v.y + v.z*v.z + v.w*v.w;
    float t = v.x*lw.x*pw.x + v.y*lw.y*pw.y + v.z*lw.z*pw.z + v.w*lw.w*pw.w;
    #pragma unroll
    for (int off = 8; off > 0; off >>= 1) {
        s += __shfl_xor_sync(FULL, s, off);
        q += __shfl_xor_sync(FULL, q, off);
        t += __shfl_xor_sync(FULL, t, off);
    }
    if (j == 0) {
        int g = batch[n];
        atomicAdd(&sS[g], t);
        atomicAdd(&sC[g], 1);
        atomicAdd(&sSum, s);
        atomicAdd(&sSq,  q);
    }
    __syncthreads();

    if (tid < N_GRAPHS && sC[tid] != 0) {
        atomicAdd(&g_S[tid], (double)sS[tid]);
        atomicAdd(&g_cnt[tid], sC[tid]);
    }
    if (tid == 0) {
        atomicAdd(&g_sum, (double)sSum);
        atomicAdd(&g_sq,  (double)sSq);
    }
}

// -------- kernel 5: final scalar combine + sigmoid --------
__global__ void k_final(float* __restrict__ out) {
    int t = threadIdx.x;
    double Ntot = (double)N_NODES * HID;
    double mu_d  = g_sum / Ntot;
    double var_d = g_sq / Ntot - mu_d * mu_d;
    float mu  = (float)mu_d;
    float inv = rsqrtf((float)var_d + LN_EPS);

    float cnt = fmaxf((float)g_cnt[t], 1.f);
    float y = inv * ((float)g_S[t] / cnt - mu * g_sW) + g_sB;
    out[t] = 1.f / (1.f + __expf(-y));
}

extern "C" void kernel_launch(void* const* d_in, const int* in_sizes, int n_in,
                              void* d_out, int out_size) {
    const float* x         = (const float*)d_in[0];
    const int*   ei        = (const int*)  d_in[1];
    const int*   batch     = (const int*)  d_in[2];
    const float* W_l       = (const float*)d_in[3];
    const float* b_l       = (const float*)d_in[4];
    const float* W_r       = (const float*)d_in[5];
    const float* b_r       = (const float*)d_in[6];
    const float* att       = (const float*)d_in[7];
    const float* conv_bias = (const float*)d_in[8];
    const float* ln_w      = (const float*)d_in[9];
    const float* ln_b      = (const float*)d_in[10];
    const float* lin_w     = (const float*)d_in[11];
    const float* lin_b     = (const float*)d_in[12];
    float* out = (float*)d_out;

    k_zero<<<512, 256>>>();
    k_const<<<1, 32>>>(W_l, att, ln_w, ln_b, lin_w, lin_b);
    k_prehalf<<<N_NODES / 16, 256>>>(x, W_l, W_r, att, b_l, b_r);
    k_edge<<<EDGE_BLOCKS, 256>>>(ei, att);
    k_node<<<N_NODES / 16, 256>>>(W_l, b_l, conv_bias, ln_w, lin_w, batch);
    k_final<<<1, N_GRAPHS>>>(out);
}